// round 14
// baseline (speedup 1.0000x reference)
#include <cuda_runtime.h>

#define NCH    129
#define T      64000
#define BS     8
#define NFRM   250
#define NCHUNK 69
#define CHUNK  928       // multiple of 4; last chunk clamps at T
#define WARM   288       // z warm; 0.97^288 = e^-8.8
#define WARMW  96        // w warm (beta^96 = e^-12)
#define NSTREAM 17       // 16 regular (4 ch-groups x 4 pairs) + 1 combined

#define ALPHA  0.992217938260243520f   // exp(-1/128)
#define BETA   0.882496902584595400f   // exp(-1/8)

#define Q1     7.1017e-4f              // alpha^928 = e^-7.25 (q^2 ~ 5e-7: dropped)
#define INV128 0.0078125f

typedef unsigned long long u64;

// Per-chunk local-alpha-IIR tail sums: S[c][b][ch]
__device__ float g_S[NCHUNK * BS * NCH];

__device__ __forceinline__ u64 pack2(float lo, float hi) {
    u64 r; asm("mov.b64 %0, {%1, %2};" : "=l"(r) : "f"(lo), "f"(hi)); return r;
}
__device__ __forceinline__ void unpack2(u64 v, float& lo, float& hi) {
    asm("mov.b64 {%0, %1}, %2;" : "=f"(lo), "=f"(hi) : "l"(v));
}
#define FMA2(d,a,b,c) asm("fma.rn.f32x2 %0, %1, %2, %3;" : "=l"(d) : "l"(a), "l"(b), "l"(c))
#define MUL2(d,a,b)   asm("mul.rn.f32x2 %0, %1, %2;"     : "=l"(d) : "l"(a), "l"(b))
__device__ __forceinline__ float tanha(float x) {
    float r; asm("tanh.approx.f32 %0, %1;" : "=f"(r) : "f"(x)); return r;
}

__global__ __launch_bounds__(128)
void aud_spec_kernel(const float* __restrict__ wav,
                     const float* __restrict__ cB,
                     const float* __restrict__ cA,
                     float* __restrict__ out)
{
    const int warpId = blockIdx.x * 4 + (threadIdx.x >> 5);
    if (warpId >= NSTREAM * NCHUNK) return;          // pad warps
    const int c    = warpId / NSTREAM;
    const int s    = warpId % NSTREAM;
    const int lane = threadIdx.x & 31;

    // Stream decode:
    //   s < 16 : regular — ch-group w = s&3, batch-pair p = s>>2,
    //            ch = 31*w + lane (max 124); lane 0 of w>0 is boundary dup.
    //   s == 16: combined tail — lane = 5*pp + j covers pair pp, ch 124+j
    //            (j=0 boundary dup, j=1..4 -> ch 125..128); lanes >= 20 idle.
    int p, ch;
    bool doStore;
    if (s < 16) {
        const int w = s & 3;
        p  = s >> 2;
        ch = 31 * w + lane;
        doStore = (lane > 0) || (w == 0);
    } else {
        const bool valid = lane < 20;
        const int pp = valid ? (lane / 5) : 3;
        const int j  = valid ? (lane - 5 * pp) : 4;
        p  = pp;
        ch = 124 + j;
        doStore = valid && (j > 0);
    }

    const float* Bc = cB + ch * 5;
    const float* Ac = cA + ch * 5;
    // Fold the sigmoid's 1/2 argument scale into B (tanh form).
    const float b0 = 0.5f * Bc[0], b1 = 0.5f * Bc[1], b2 = 0.5f * Bc[2],
                b3 = 0.5f * Bc[3], b4 = 0.5f * Bc[4];
    const u64 B0p = pack2(b0, b0), B1p = pack2(b1, b1), B2p = pack2(b2, b2),
              B3p = pack2(b3, b3), B4p = pack2(b4, b4);
    const u64 A1p = pack2(-Ac[1], -Ac[1]);
    const u64 A2p = pack2(-Ac[2], -Ac[2]);
    const u64 A3p = pack2(-Ac[3], -Ac[3]);
    const u64 A4p = pack2(-Ac[4], -Ac[4]);

    u64 z0 = 0, z1 = 0, z2 = 0, z3 = 0;   // packed IIR state (TDF-II)
    float w0 = 0.f, w1 = 0.f;              // w = beta*w + tanh(y)
    float u0 = 0.f, u1 = 0.f;              // scaled alpha IIR (local)

    const float4* xa4 = reinterpret_cast<const float4*>(wav + (2 * p)     * T);
    const float4* xb4 = reinterpret_cast<const float4*>(wav + (2 * p + 1) * T);

    const int cstart = c * CHUNK;
    int cend = cstart + CHUNK;
    if (cend > T) cend = T;
    int ws = cstart - WARM;
    if (ws < 0) ws = 0;
    int wsw = cstart - WARMW;
    if (wsw < 0) wsw = 0;

    float* outA = out + ((2 * p)     * NCH + ch) * NFRM;
    float* outB = out + ((2 * p + 1) * NCH + ch) * NFRM;

// IIR core (TDF-II, packed)
#define IIR(xx, y_) {                                                  \
    u64 t1_, t2_, t3_, t4_;                                            \
    FMA2(y_,  B0p, (xx), z0);                                          \
    FMA2(t1_, B1p, (xx), z1);                                          \
    FMA2(t2_, B2p, (xx), z2);                                          \
    FMA2(t3_, B3p, (xx), z3);                                          \
    MUL2(t4_, B4p, (xx));                                              \
    FMA2(z0, A1p, y_, t1_);                                            \
    FMA2(z1, A2p, y_, t2_);                                            \
    FMA2(z2, A3p, y_, t3_);                                            \
    FMA2(z3, A4p, y_, t4_);                                            \
}
#define STEP_Z(xx) { u64 y_; IIR(xx, y_); (void)y_; }
#define STEP_ZW(xx) {                                                  \
    u64 y_; IIR(xx, y_);                                               \
    float y0_, y1_; unpack2(y_, y0_, y1_);                             \
    w0 = fmaf(BETA, w0, tanha(y0_));                                   \
    w1 = fmaf(BETA, w1, tanha(y1_));                                   \
}
// Software-pipelined shfl: consume LAST step's pending shfl (wq,pw),
// then issue this step's shfl. u lags by one step.
#define STEP_P(xx) {                                                   \
    u64 y_; IIR(xx, y_);                                               \
    float y0_, y1_; unpack2(y_, y0_, y1_);                             \
    w0 = fmaf(BETA, w0, tanha(y0_));                                   \
    w1 = fmaf(BETA, w1, tanha(y1_));                                   \
    u0 = fmaf(ALPHA, u0, fmaxf(wq0 - pw0, 0.0f));                      \
    u1 = fmaf(ALPHA, u1, fmaxf(wq1 - pw1, 0.0f));                      \
    pw0 = __shfl_up_sync(0xffffffffu, w0, 1);                          \
    pw1 = __shfl_up_sync(0xffffffffu, w1, 1);                          \
    wq0 = w0; wq1 = w1;                                                \
}

    int g = ws >> 2;                     // group index (4 samples/group)
    const int gWWEnd  = wsw >> 2;
    const int gWarmEnd = cstart >> 2;
    const int gEnd = cend >> 2;
    const int gLast = (T >> 2) - 1;

    float4 a = __ldg(xa4 + g);
    float4 b = __ldg(xb4 + g);

    // Phase A: settle poles only.
    for (; g < gWWEnd; ) {
        const int gn = g + 1;
        const float4 an = __ldg(xa4 + gn);
        const float4 bn = __ldg(xb4 + gn);
        STEP_Z(pack2(a.x, b.x)); STEP_Z(pack2(a.y, b.y));
        STEP_Z(pack2(a.z, b.z)); STEP_Z(pack2(a.w, b.w));
        a = an; b = bn; g = gn;
    }

    // Phase B: settle beta state w.
    for (; g < gWarmEnd; ) {
        const int gn = g + 1;
        const float4 an = __ldg(xa4 + gn);
        const float4 bn = __ldg(xb4 + gn);
        STEP_ZW(pack2(a.x, b.x)); STEP_ZW(pack2(a.y, b.y));
        STEP_ZW(pack2(a.z, b.z)); STEP_ZW(pack2(a.w, b.w));
        a = an; b = bn; g = gn;
    }
    u0 = 0.f; u1 = 0.f;                  // zero-init local alpha IIR
    float wq0 = w0, wq1 = w1;            // prime shfl pipeline (no-op consume)
    float pw0 = w0, pw1 = w1;

    // Phase C: frames at g % 64 == 0 (t % 256 == 0), any chunk alignment.
    for (; g < gEnd; g++) {
        const int gn = (g + 1 > gLast) ? gLast : g + 1;
        const float4 an = __ldg(xa4 + gn);
        const float4 bn = __ldg(xb4 + gn);
        STEP_P(pack2(a.x, b.x));
        if ((g & 63) == 0) {
            if (doStore) {
                const float us0 = fmaf(ALPHA, u0, fmaxf(wq0 - pw0, 0.0f));
                const float us1 = fmaf(ALPHA, u1, fmaxf(wq1 - pw1, 0.0f));
                outA[g >> 6] = 0.5f * us0;
                outB[g >> 6] = 0.5f * us1;
            }
        }
        STEP_P(pack2(a.y, b.y));
        STEP_P(pack2(a.z, b.z));
        STEP_P(pack2(a.w, b.w));
        a = an; b = bn;
    }

    // Final flush: include the last step's pending diff, then emit S_c.
    u0 = fmaf(ALPHA, u0, fmaxf(wq0 - pw0, 0.0f));
    u1 = fmaf(ALPHA, u1, fmaxf(wq1 - pw1, 0.0f));
#undef STEP_P
#undef STEP_ZW
#undef STEP_Z
#undef IIR

    if (doStore) {
        g_S[(c * BS + 2 * p)     * NCH + ch] = 0.5f * u0;
        g_S[(c * BS + 2 * p + 1) * NCH + ch] = 0.5f * u1;
    }
}

// Fully parallel correction, one thread per output frame:
//   c = (256 f) / CHUNK; o = 256 f - c*CHUNK
//   U(c) = S[c-1] + q * S[c-2]        (q = alpha^CHUNK = e^-7.25)
//   out[.., f] += alpha^(o+1) * U(c)
__global__ void fixup_kernel(float* __restrict__ out)
{
    int tid = blockIdx.x * blockDim.x + threadIdx.x;   // (b*NCH+ch)*NFRM + f
    if (tid >= BS * NCH * NFRM) return;
    const int f    = tid % NFRM;
    const int base = tid / NFRM;        // b*NCH + ch

    const int t = f << 8;               // 256*f
    const int c = t / CHUNK;
    if (c == 0) return;                 // U(0) = 0

    float U = g_S[(c - 1) * (BS * NCH) + base];
    if (c >= 2) U = fmaf(Q1, g_S[(c - 2) * (BS * NCH) + base], U);

    const int o = t - c * CHUNK;
    const float pw = __expf(-(float)(o + 1) * INV128);
    out[tid] += pw * U;
}

extern "C" void kernel_launch(void* const* d_in, const int* in_sizes, int n_in,
                              void* d_out, int out_size)
{
    const float* wav = (const float*)d_in[0];   // (BS, T)
    const float* cB  = (const float*)d_in[1];   // (NCH, 5)
    const float* cA  = (const float*)d_in[2];   // (NCH, 5)
    float* out = (float*)d_out;                 // (BS, NCH, NFRM)

    const int nWarps = NSTREAM * NCHUNK;        // 1173
    const int nBlocks = (nWarps + 3) / 4;       // 294 = 147 SMs x 2
    aud_spec_kernel<<<nBlocks, 128>>>(wav, cB, cA, out);

    const int nFix = BS * NCH * NFRM;
    fixup_kernel<<<(nFix + 255) / 256, 256>>>(out);
}

// round 15
// speedup vs baseline: 1.0128x; 1.0128x over previous
#include <cuda_runtime.h>

#define NCH    129
#define T      64000
#define BS     8
#define NFRM   250
#define NCHUNK 69
#define CHUNK  928       // multiple of 4; last chunk clamps at T
#define WARM   288       // z warm; 0.97^288 = e^-8.8
#define WARMW  96        // w warm (beta^96 = e^-12)
#define NSTREAM 17       // 16 regular (4 ch-groups x 4 pairs) + 1 combined

#define ALPHA  0.992217938260243520f   // exp(-1/128)
#define BETA   0.882496902584595400f   // exp(-1/8)

#define Q1     7.1017e-4f              // alpha^928 = e^-7.25 (q^2 ~ 5e-7: dropped)
#define INV128 0.0078125f

typedef unsigned long long u64;

// Per-chunk local-alpha-IIR tail sums: S[c][b][ch]
__device__ float g_S[NCHUNK * BS * NCH];

__device__ __forceinline__ u64 pack2(float lo, float hi) {
    u64 r; asm("mov.b64 %0, {%1, %2};" : "=l"(r) : "f"(lo), "f"(hi)); return r;
}
__device__ __forceinline__ void unpack2(u64 v, float& lo, float& hi) {
    asm("mov.b64 {%0, %1}, %2;" : "=f"(lo), "=f"(hi) : "l"(v));
}
#define FMA2(d,a,b,c) asm("fma.rn.f32x2 %0, %1, %2, %3;" : "=l"(d) : "l"(a), "l"(b), "l"(c))
#define MUL2(d,a,b)   asm("mul.rn.f32x2 %0, %1, %2;"     : "=l"(d) : "l"(a), "l"(b))
__device__ __forceinline__ float tanha(float x) {
    float r; asm("tanh.approx.f32 %0, %1;" : "=f"(r) : "f"(x)); return r;
}

__global__ __launch_bounds__(128)
void aud_spec_kernel(const float* __restrict__ wav,
                     const float* __restrict__ cB,
                     const float* __restrict__ cA,
                     float* __restrict__ out)
{
    const int warpId = blockIdx.x * 4 + (threadIdx.x >> 5);
    if (warpId >= NSTREAM * NCHUNK) return;          // pad warps
    const int c    = warpId / NSTREAM;
    const int s    = warpId % NSTREAM;
    const int lane = threadIdx.x & 31;

    // Stream decode:
    //   s < 16 : regular — ch-group w = s&3, batch-pair p = s>>2,
    //            ch = 31*w + lane (max 124); lane 0 of w>0 is boundary dup.
    //   s == 16: combined tail — lane = 5*pp + j covers pair pp, ch 124+j
    //            (j=0 boundary dup, j=1..4 -> ch 125..128); lanes >= 20 idle.
    int p, ch;
    bool doStore;
    if (s < 16) {
        const int w = s & 3;
        p  = s >> 2;
        ch = 31 * w + lane;
        doStore = (lane > 0) || (w == 0);
    } else {
        const bool valid = lane < 20;
        const int pp = valid ? (lane / 5) : 3;
        const int j  = valid ? (lane - 5 * pp) : 4;
        p  = pp;
        ch = 124 + j;
        doStore = valid && (j > 0);
    }

    const float* Bc = cB + ch * 5;
    const float* Ac = cA + ch * 5;
    // Fold the sigmoid's 1/2 argument scale into B (tanh form).
    const float b0 = 0.5f * Bc[0], b1 = 0.5f * Bc[1], b2 = 0.5f * Bc[2],
                b3 = 0.5f * Bc[3], b4 = 0.5f * Bc[4];
    const u64 B0p = pack2(b0, b0), B1p = pack2(b1, b1), B2p = pack2(b2, b2),
              B3p = pack2(b3, b3), B4p = pack2(b4, b4);
    const u64 A1p = pack2(-Ac[1], -Ac[1]);
    const u64 A2p = pack2(-Ac[2], -Ac[2]);
    const u64 A3p = pack2(-Ac[3], -Ac[3]);
    const u64 A4p = pack2(-Ac[4], -Ac[4]);

    u64 z0 = 0, z1 = 0, z2 = 0, z3 = 0;   // packed IIR state (TDF-II)
    float w0 = 0.f, w1 = 0.f;              // w = beta*w + tanh(y)
    float u0 = 0.f, u1 = 0.f;              // scaled alpha IIR (local)

    const float4* xa4 = reinterpret_cast<const float4*>(wav + (2 * p)     * T);
    const float4* xb4 = reinterpret_cast<const float4*>(wav + (2 * p + 1) * T);

    const int cstart = c * CHUNK;
    int cend = cstart + CHUNK;
    if (cend > T) cend = T;
    int ws = cstart - WARM;
    if (ws < 0) ws = 0;
    int wsw = cstart - WARMW;
    if (wsw < 0) wsw = 0;

    float* outA = out + ((2 * p)     * NCH + ch) * NFRM;
    float* outB = out + ((2 * p + 1) * NCH + ch) * NFRM;

// IIR core (TDF-II, packed)
#define IIR(xx, y_) {                                                  \
    u64 t1_, t2_, t3_, t4_;                                            \
    FMA2(y_,  B0p, (xx), z0);                                          \
    FMA2(t1_, B1p, (xx), z1);                                          \
    FMA2(t2_, B2p, (xx), z2);                                          \
    FMA2(t3_, B3p, (xx), z3);                                          \
    MUL2(t4_, B4p, (xx));                                              \
    FMA2(z0, A1p, y_, t1_);                                            \
    FMA2(z1, A2p, y_, t2_);                                            \
    FMA2(z2, A3p, y_, t3_);                                            \
    FMA2(z3, A4p, y_, t4_);                                            \
}
#define STEP_Z(xx) { u64 y_; IIR(xx, y_); (void)y_; }
#define STEP_ZW(xx) {                                                  \
    u64 y_; IIR(xx, y_);                                               \
    float y0_, y1_; unpack2(y_, y0_, y1_);                             \
    w0 = fmaf(BETA, w0, tanha(y0_));                                   \
    w1 = fmaf(BETA, w1, tanha(y1_));                                   \
}
// Software-pipelined shfl: consume LAST step's pending shfl (wq,pw),
// then issue this step's shfl. u lags by one step.
#define STEP_P(xx) {                                                   \
    u64 y_; IIR(xx, y_);                                               \
    float y0_, y1_; unpack2(y_, y0_, y1_);                             \
    w0 = fmaf(BETA, w0, tanha(y0_));                                   \
    w1 = fmaf(BETA, w1, tanha(y1_));                                   \
    u0 = fmaf(ALPHA, u0, fmaxf(wq0 - pw0, 0.0f));                      \
    u1 = fmaf(ALPHA, u1, fmaxf(wq1 - pw1, 0.0f));                      \
    pw0 = __shfl_up_sync(0xffffffffu, w0, 1);                          \
    pw1 = __shfl_up_sync(0xffffffffu, w1, 1);                          \
    wq0 = w0; wq1 = w1;                                                \
}

    int g = ws >> 2;                     // group index (4 samples/group)
    const int gWWEnd  = wsw >> 2;
    const int gWarmEnd = cstart >> 2;
    const int gEnd = cend >> 2;
    const int gLast = (T >> 2) - 1;

    float4 a = __ldg(xa4 + g);
    float4 b = __ldg(xb4 + g);

    // Phase A: settle poles only.
    for (; g < gWWEnd; ) {
        const int gn = g + 1;
        const float4 an = __ldg(xa4 + gn);
        const float4 bn = __ldg(xb4 + gn);
        STEP_Z(pack2(a.x, b.x)); STEP_Z(pack2(a.y, b.y));
        STEP_Z(pack2(a.z, b.z)); STEP_Z(pack2(a.w, b.w));
        a = an; b = bn; g = gn;
    }

    // Phase B: settle beta state w.
    for (; g < gWarmEnd; ) {
        const int gn = g + 1;
        const float4 an = __ldg(xa4 + gn);
        const float4 bn = __ldg(xb4 + gn);
        STEP_ZW(pack2(a.x, b.x)); STEP_ZW(pack2(a.y, b.y));
        STEP_ZW(pack2(a.z, b.z)); STEP_ZW(pack2(a.w, b.w));
        a = an; b = bn; g = gn;
    }
    u0 = 0.f; u1 = 0.f;                  // zero-init local alpha IIR
    float wq0 = w0, wq1 = w1;            // prime shfl pipeline (no-op consume)
    float pw0 = w0, pw1 = w1;

    // Phase C: frames at g % 64 == 0 (t % 256 == 0), any chunk alignment.
    for (; g < gEnd; g++) {
        const int gn = (g + 1 > gLast) ? gLast : g + 1;
        const float4 an = __ldg(xa4 + gn);
        const float4 bn = __ldg(xb4 + gn);
        STEP_P(pack2(a.x, b.x));
        if ((g & 63) == 0) {
            if (doStore) {
                const float us0 = fmaf(ALPHA, u0, fmaxf(wq0 - pw0, 0.0f));
                const float us1 = fmaf(ALPHA, u1, fmaxf(wq1 - pw1, 0.0f));
                outA[g >> 6] = 0.5f * us0;
                outB[g >> 6] = 0.5f * us1;
            }
        }
        STEP_P(pack2(a.y, b.y));
        STEP_P(pack2(a.z, b.z));
        STEP_P(pack2(a.w, b.w));
        a = an; b = bn;
    }

    // Final flush: include the last step's pending diff, then emit S_c.
    u0 = fmaf(ALPHA, u0, fmaxf(wq0 - pw0, 0.0f));
    u1 = fmaf(ALPHA, u1, fmaxf(wq1 - pw1, 0.0f));
#undef STEP_P
#undef STEP_ZW
#undef STEP_Z
#undef IIR

    if (doStore) {
        g_S[(c * BS + 2 * p)     * NCH + ch] = 0.5f * u0;
        g_S[(c * BS + 2 * p + 1) * NCH + ch] = 0.5f * u1;
    }
}

// Fully parallel correction, one thread per output frame:
//   c = (256 f) / CHUNK; o = 256 f - c*CHUNK
//   U(c) = S[c-1] + q * S[c-2]        (q = alpha^CHUNK = e^-7.25)
//   out[.., f] += alpha^(o+1) * U(c)
__global__ void fixup_kernel(float* __restrict__ out)
{
    int tid = blockIdx.x * blockDim.x + threadIdx.x;   // (b*NCH+ch)*NFRM + f
    if (tid >= BS * NCH * NFRM) return;
    const int f    = tid % NFRM;
    const int base = tid / NFRM;        // b*NCH + ch

    const int t = f << 8;               // 256*f
    const int c = t / CHUNK;
    if (c == 0) return;                 // U(0) = 0

    float U = g_S[(c - 1) * (BS * NCH) + base];
    if (c >= 2) U = fmaf(Q1, g_S[(c - 2) * (BS * NCH) + base], U);

    const int o = t - c * CHUNK;
    const float pw = __expf(-(float)(o + 1) * INV128);
    out[tid] += pw * U;
}

extern "C" void kernel_launch(void* const* d_in, const int* in_sizes, int n_in,
                              void* d_out, int out_size)
{
    const float* wav = (const float*)d_in[0];   // (BS, T)
    const float* cB  = (const float*)d_in[1];   // (NCH, 5)
    const float* cA  = (const float*)d_in[2];   // (NCH, 5)
    float* out = (float*)d_out;                 // (BS, NCH, NFRM)

    const int nWarps = NSTREAM * NCHUNK;        // 1173
    const int nBlocks = (nWarps + 3) / 4;       // 294 = 147 SMs x 2
    aud_spec_kernel<<<nBlocks, 128>>>(wav, cB, cA, out);

    const int nFix = BS * NCH * NFRM;
    fixup_kernel<<<(nFix + 255) / 256, 256>>>(out);
}